// round 1
// baseline (speedup 1.0000x reference)
#include <cuda_runtime.h>

#define W_IMG 256
#define H_IMG 256
#define TILE 16
#define NG 8192
#define BATCH 256
#define MIN_W 1e-6f

__global__ __launch_bounds__(256, 4)
void gs_raster_kernel(const float* __restrict__ pxy,      // [N,2]
                      const float* __restrict__ icov,     // [N,2,2]
                      const float* __restrict__ radius,   // [N]
                      const float* __restrict__ colors,   // [N,3]
                      const float* __restrict__ opacity,  // [N]
                      float* __restrict__ out)            // [W,H,3]
{
    __shared__ float4 s_g1[BATCH];   // mx, my, a, b
    __shared__ float4 s_g2[BATCH];   // c, sigmoid(op), col.r, col.g
    __shared__ float  s_cb[BATCH];   // col.b
    __shared__ int    s_wcnt[8];

    const int tid  = threadIdx.x;
    const int lane = tid & 31;
    const int warp = tid >> 5;

    const float tx0 = (float)(blockIdx.x * TILE);
    const float ty0 = (float)(blockIdx.y * TILE);
    const float tx1 = tx0 + (float)TILE;
    const float ty1 = ty0 + (float)TILE;

    // pixel coords: x = tid>>4 within tile, y = tid&15 (consecutive tid -> consecutive y -> coalesced-ish out)
    const float fx = tx0 + (float)(tid >> 4);
    const float fy = ty0 + (float)(tid & 15);

    float T  = 1.0f;
    float cr = 0.0f, cg = 0.0f, cb = 0.0f;

    for (int base = 0; base < NG; base += BATCH) {
        // block-wide early exit (also serves as the barrier protecting smem reuse)
        if (__syncthreads_count(T >= MIN_W) == 0) break;

        const int g = base + tid;            // NG % BATCH == 0, always in range
        const float2 mp = ((const float2*)pxy)[g];
        const float  r  = radius[g];
        const bool keep = (floorf(mp.x - r) <= tx1) && (ceilf(mp.x + r) >= tx0)
                       && (floorf(mp.y - r) <= ty1) && (ceilf(mp.y + r) >= ty0);

        const unsigned m = __ballot_sync(0xffffffffu, keep);
        if (lane == 0) s_wcnt[warp] = __popc(m);
        __syncthreads();

        int off = 0, total = 0;
        #pragma unroll
        for (int w = 0; w < 8; ++w) {
            const int c = s_wcnt[w];
            if (w < warp) off += c;
            total += c;
        }

        if (keep) {
            const int idx = off + __popc(m & ((1u << lane) - 1u));   // order-preserving
            const float4 ic = ((const float4*)icov)[g];              // a=ic.x b=ic.y (ic.z dup) c=ic.w
            const float  sg = 1.0f / (1.0f + __expf(-opacity[g]));
            const float  c0 = colors[3 * g + 0];
            const float  c1 = colors[3 * g + 1];
            const float  c2 = colors[3 * g + 2];
            s_g1[idx] = make_float4(mp.x, mp.y, ic.x, ic.y);
            s_g2[idx] = make_float4(ic.w, sg, c0, c1);
            s_cb[idx] = c2;
        }
        __syncthreads();

        if (T >= MIN_W) {
            for (int j = 0; j < total; ++j) {
                const float4 g1 = s_g1[j];
                const float4 g2 = s_g2[j];
                const float dx = fx - g1.x;
                const float dy = fy - g1.y;
                const float q  = g1.z * dx * dx + 2.0f * g1.w * dx * dy + g2.x * dy * dy;
                const float alpha = __expf(-0.5f * q) * g2.y;
                const float Tn = T * (1.0f - alpha);
                if (Tn >= MIN_W) {
                    const float w = T * alpha;
                    cr = fmaf(w, g2.z, cr);
                    cg = fmaf(w, g2.w, cg);
                    cb = fmaf(w, s_cb[j], cb);
                }
                T = Tn;
                if (T < MIN_W) break;   // monotone: no later gaussian can contribute
            }
        }
    }

    const int px = blockIdx.x * TILE + (tid >> 4);
    const int py = blockIdx.y * TILE + (tid & 15);
    const int o  = (px * H_IMG + py) * 3;
    out[o + 0] = cr;
    out[o + 1] = cg;
    out[o + 2] = cb;
}

extern "C" void kernel_launch(void* const* d_in, const int* in_sizes, int n_in,
                              void* d_out, int out_size) {
    const float* pxy     = (const float*)d_in[0];  // points_xy      [8192,2]
    const float* icov    = (const float*)d_in[1];  // inverse_cov    [8192,2,2]
    const float* radius  = (const float*)d_in[2];  // radius         [8192]
    const float* colors  = (const float*)d_in[3];  // colors         [8192,3]
    const float* opacity = (const float*)d_in[4];  // opacity        [8192]
    float* out = (float*)d_out;                    // [256,256,3]

    dim3 grid(W_IMG / TILE, H_IMG / TILE);
    gs_raster_kernel<<<grid, 256>>>(pxy, icov, radius, colors, opacity, out);
}

// round 2
// speedup vs baseline: 1.5131x; 1.5131x over previous
#include <cuda_runtime.h>

#define W_IMG 256
#define H_IMG 256
#define TILE 16
#define NG 8192
#define BATCH 256
#define MIN_W 1e-6f
#define UNROLL 8
#define LOG2E 1.4426950408889634f

__device__ __forceinline__ float ex2_fast(float x) {
    float y;
    asm("ex2.approx.f32 %0, %1;" : "=f"(y) : "f"(x));
    return y;
}
__device__ __forceinline__ float lg2_fast(float x) {
    float y;
    asm("lg2.approx.f32 %0, %1;" : "=f"(y) : "f"(x));
    return y;
}

__global__ __launch_bounds__(256)
void gs_raster_kernel(const float* __restrict__ pxy,      // [N,2]
                      const float* __restrict__ icov,     // [N,2,2]
                      const float* __restrict__ radius,   // [N]
                      const float* __restrict__ colors,   // [N,3]
                      const float* __restrict__ opacity,  // [N]
                      float* __restrict__ out)            // [W,H,3]
{
    __shared__ float4 s_g1[BATCH];   // mx, my, a2, b2
    __shared__ float4 s_g2[BATCH];   // c2, d,  col.r, col.g
    __shared__ float  s_cb[BATCH];   // col.b
    __shared__ int    s_wcnt[8];

    const int tid  = threadIdx.x;
    const int lane = tid & 31;
    const int warp = tid >> 5;

    const float tx0 = (float)(blockIdx.x * TILE);
    const float ty0 = (float)(blockIdx.y * TILE);
    const float tx1 = tx0 + (float)TILE;
    const float ty1 = ty0 + (float)TILE;

    const float fx = tx0 + (float)(tid >> 4);
    const float fy = ty0 + (float)(tid & 15);

    float T  = 1.0f;
    float cr = 0.0f, cg = 0.0f, cb = 0.0f;

    for (int base = 0; base < NG; base += BATCH) {
        // block-wide early exit; also the barrier protecting smem reuse
        if (__syncthreads_count(T >= MIN_W) == 0) break;

        const int g = base + tid;                      // NG % BATCH == 0
        const float2 mp = ((const float2*)pxy)[g];
        const float  r  = radius[g];
        const bool keep = (floorf(mp.x - r) <= tx1) && (ceilf(mp.x + r) >= tx0)
                       && (floorf(mp.y - r) <= ty1) && (ceilf(mp.y + r) >= ty0);

        const unsigned m = __ballot_sync(0xffffffffu, keep);
        if (lane == 0) s_wcnt[warp] = __popc(m);
        __syncthreads();

        int off = 0, total = 0;
        #pragma unroll
        for (int w = 0; w < 8; ++w) {
            const int c = s_wcnt[w];
            if (w < warp) off += c;
            total += c;
        }
        const int padded = (total + (UNROLL - 1)) & ~(UNROLL - 1);

        if (keep) {
            const int idx = off + __popc(m & ((1u << lane) - 1u));   // order-preserving
            const float4 ic = ((const float4*)icov)[g];              // a=ic.x b=ic.y c=ic.w
            // fold -0.5, log2(e), and sigmoid into the exponent:
            const float a2 = -0.5f * LOG2E * ic.x;
            const float b2 = -LOG2E * ic.y;
            const float c2 = -0.5f * LOG2E * ic.w;
            const float d  = -lg2_fast(1.0f + ex2_fast(-LOG2E * opacity[g])); // log2(sigmoid(op))
            s_g1[idx] = make_float4(mp.x, mp.y, a2, b2);
            s_g2[idx] = make_float4(c2, d, colors[3*g+0], colors[3*g+1]);
            s_cb[idx] = colors[3*g+2];
        }
        // sentinel padding: alpha == 0 exactly (ex2(-1e30) -> 0)
        if (tid >= total && tid < padded) {
            s_g1[tid] = make_float4(0.0f, 0.0f, 0.0f, 0.0f);
            s_g2[tid] = make_float4(0.0f, -1e30f, 0.0f, 0.0f);
            s_cb[tid] = 0.0f;
        }
        __syncthreads();

        if (T >= MIN_W) {
            for (int j = 0; j < padded; j += UNROLL) {
                float al[UNROLL];
                // speculative, independent alpha evaluation (fills FMA + MUFU pipes)
                #pragma unroll
                for (int k = 0; k < UNROLL; ++k) {
                    const float4 g1 = s_g1[j + k];
                    const float4 g2 = s_g2[j + k];
                    const float dx = fx - g1.x;
                    const float dy = fy - g1.y;
                    float u = fmaf(g1.z, dx, g1.w * dy);     // a2*dx + b2*dy
                    float q = fmaf(g2.x, dy * dy, g2.y);     // c2*dy^2 + d
                    q = fmaf(u, dx, q);
                    al[k] = ex2_fast(q);                      // = exp(-q/2)*sigmoid(op)
                }
                // short serial T-chain + color accumulation (off critical path)
                #pragma unroll
                for (int k = 0; k < UNROLL; ++k) {
                    const float Tn = fmaf(-al[k], T, T);      // T*(1-alpha)
                    const float w  = (Tn >= MIN_W) ? T * al[k] : 0.0f;
                    const float4 g2 = s_g2[j + k];
                    cr = fmaf(w, g2.z, cr);
                    cg = fmaf(w, g2.w, cg);
                    cb = fmaf(w, s_cb[j + k], cb);
                    T = Tn;
                }
                if (T < MIN_W) break;     // monotone: later gaussians can't contribute
            }
        }
    }

    const int px = blockIdx.x * TILE + (tid >> 4);
    const int py = blockIdx.y * TILE + (tid & 15);
    const int o  = (px * H_IMG + py) * 3;
    out[o + 0] = cr;
    out[o + 1] = cg;
    out[o + 2] = cb;
}

extern "C" void kernel_launch(void* const* d_in, const int* in_sizes, int n_in,
                              void* d_out, int out_size) {
    const float* pxy     = (const float*)d_in[0];
    const float* icov    = (const float*)d_in[1];
    const float* radius  = (const float*)d_in[2];
    const float* colors  = (const float*)d_in[3];
    const float* opacity = (const float*)d_in[4];
    float* out = (float*)d_out;

    dim3 grid(W_IMG / TILE, H_IMG / TILE);
    gs_raster_kernel<<<grid, 256>>>(pxy, icov, radius, colors, opacity, out);
}

// round 3
// speedup vs baseline: 1.5425x; 1.0194x over previous
#include <cuda_runtime.h>

#define W_IMG 256
#define H_IMG 256
#define TILE 16
#define NG 8192
#define BATCH 256
#define MIN_W 1e-6f
#define LOG2E 1.4426950408889634f

typedef unsigned long long u64;

__device__ __forceinline__ float ex2_fast(float x) {
    float y; asm("ex2.approx.f32 %0, %1;" : "=f"(y) : "f"(x)); return y;
}
__device__ __forceinline__ float lg2_fast(float x) {
    float y; asm("lg2.approx.f32 %0, %1;" : "=f"(y) : "f"(x)); return y;
}
__device__ __forceinline__ u64 pack2(float lo, float hi) {
    u64 r; asm("mov.b64 %0, {%1, %2};" : "=l"(r) : "f"(lo), "f"(hi)); return r;
}
__device__ __forceinline__ void unpack2(u64 v, float& lo, float& hi) {
    asm("mov.b64 {%0, %1}, %2;" : "=f"(lo), "=f"(hi) : "l"(v));
}
__device__ __forceinline__ u64 f2add(u64 a, u64 b) {
    u64 d; asm("add.rn.f32x2 %0, %1, %2;" : "=l"(d) : "l"(a), "l"(b)); return d;
}
__device__ __forceinline__ u64 f2mul(u64 a, u64 b) {
    u64 d; asm("mul.rn.f32x2 %0, %1, %2;" : "=l"(d) : "l"(a), "l"(b)); return d;
}
__device__ __forceinline__ u64 f2fma(u64 a, u64 b, u64 c) {
    u64 d; asm("fma.rn.f32x2 %0, %1, %2, %3;" : "=l"(d) : "l"(a), "l"(b), "l"(c)); return d;
}

__global__ __launch_bounds__(256)
void gs_raster_kernel(const float* __restrict__ pxy,      // [N,2]
                      const float* __restrict__ icov,     // [N,2,2]
                      const float* __restrict__ radius,   // [N]
                      const float* __restrict__ colors,   // [N,3]
                      const float* __restrict__ opacity,  // [N]
                      float* __restrict__ out)            // [W,H,3]
{
    // pair-interleaved layout: slot j holds gaussians (2j, 2j+1)
    __shared__ ulonglong2 s_m [BATCH/2];  // (-mx pair), (-my pair)
    __shared__ ulonglong2 s_ab[BATCH/2];  // (a2 pair), (b2 pair)
    __shared__ ulonglong2 s_cd[BATCH/2];  // (c2 pair), (d pair)
    __shared__ ulonglong2 s_rg[BATCH/2];  // (r,g of even), (r,g of odd)
    __shared__ float2     s_b [BATCH/2];  // (cb even, cb odd)
    __shared__ int        s_wcnt[8];

    const int tid  = threadIdx.x;
    const int lane = tid & 31;
    const int warp = tid >> 5;

    const float tx0 = (float)(blockIdx.x * TILE);
    const float ty0 = (float)(blockIdx.y * TILE);
    const float tx1 = tx0 + (float)TILE;
    const float ty1 = ty0 + (float)TILE;

    const float fx = tx0 + (float)(tid >> 4);
    const float fy = ty0 + (float)(tid & 15);
    const u64 fxp = pack2(fx, fx);
    const u64 fyp = pack2(fy, fy);

    float T = 1.0f;
    u64   crg = pack2(0.0f, 0.0f);   // packed (cr, cg) accumulator
    float cb  = 0.0f;

    for (int base = 0; base < NG; base += BATCH) {
        if (__syncthreads_count(T >= MIN_W) == 0) break;

        const int g = base + tid;
        const float2 mp = ((const float2*)pxy)[g];
        const float  r  = radius[g];
        const bool keep = (floorf(mp.x - r) <= tx1) && (ceilf(mp.x + r) >= tx0)
                       && (floorf(mp.y - r) <= ty1) && (ceilf(mp.y + r) >= ty0);

        const unsigned m = __ballot_sync(0xffffffffu, keep);
        if (lane == 0) s_wcnt[warp] = __popc(m);
        __syncthreads();

        int off = 0, total = 0;
        #pragma unroll
        for (int w = 0; w < 8; ++w) {
            const int c = s_wcnt[w];
            if (w < warp) off += c;
            total += c;
        }
        const int padded = (total + 7) & ~7;

        if (keep) {
            const int idx = off + __popc(m & ((1u << lane) - 1u));
            const int j = idx >> 1, e = idx & 1;
            const float4 ic = ((const float4*)icov)[g];
            const float a2 = -0.5f * LOG2E * ic.x;
            const float b2 = -LOG2E * ic.y;
            const float c2 = -0.5f * LOG2E * ic.w;
            const float d  = -lg2_fast(1.0f + ex2_fast(-LOG2E * opacity[g]));
            float* pm  = (float*)&s_m[j];  pm[e]  = -mp.x; pm[2+e]  = -mp.y;
            float* pab = (float*)&s_ab[j]; pab[e] = a2;    pab[2+e] = b2;
            float* pcd = (float*)&s_cd[j]; pcd[e] = c2;    pcd[2+e] = d;
            float* prg = (float*)&s_rg[j]; prg[2*e] = colors[3*g+0]; prg[2*e+1] = colors[3*g+1];
            ((float*)&s_b[j])[e] = colors[3*g+2];
        }
        // sentinel: alpha == 0 exactly (ex2(-1e30) -> 0)
        if (tid >= total && tid < padded) {
            const int j = tid >> 1, e = tid & 1;
            float* pm  = (float*)&s_m[j];  pm[e]  = 0.0f; pm[2+e]  = 0.0f;
            float* pab = (float*)&s_ab[j]; pab[e] = 0.0f; pab[2+e] = 0.0f;
            float* pcd = (float*)&s_cd[j]; pcd[e] = 0.0f; pcd[2+e] = -1e30f;
            float* prg = (float*)&s_rg[j]; prg[2*e] = 0.0f; prg[2*e+1] = 0.0f;
            ((float*)&s_b[j])[e] = 0.0f;
        }
        __syncthreads();

        if (T >= MIN_W) {
            const int npair = padded >> 1;
            for (int j = 0; j < npair; j += 4) {   // 4 pairs = 8 gaussians
                float al[8];
                #pragma unroll
                for (int p = 0; p < 4; ++p) {
                    const ulonglong2 mm = s_m [j + p];
                    const ulonglong2 ab = s_ab[j + p];
                    const ulonglong2 cd = s_cd[j + p];
                    const u64 dx = f2add(fxp, mm.x);
                    const u64 dy = f2add(fyp, mm.y);
                    const u64 t1 = f2fma(ab.x, dx, f2mul(ab.y, dy));      // a2*dx + b2*dy
                    const u64 t2 = f2fma(f2mul(cd.x, dy), dy, cd.y);      // c2*dy^2 + d
                    const u64 q  = f2fma(t1, dx, t2);
                    float q0, q1; unpack2(q, q0, q1);
                    al[2*p]   = ex2_fast(q0);
                    al[2*p+1] = ex2_fast(q1);
                }
                #pragma unroll
                for (int p = 0; p < 4; ++p) {
                    const ulonglong2 rg = s_rg[j + p];
                    const float2     bb = s_b [j + p];
                    {   // even gaussian
                        const float a  = al[2*p];
                        const float Tn = fmaf(-a, T, T);
                        const float w  = (Tn >= MIN_W) ? T * a : 0.0f;
                        crg = f2fma(pack2(w, w), rg.x, crg);
                        cb  = fmaf(w, bb.x, cb);
                        T = Tn;
                    }
                    {   // odd gaussian
                        const float a  = al[2*p+1];
                        const float Tn = fmaf(-a, T, T);
                        const float w  = (Tn >= MIN_W) ? T * a : 0.0f;
                        crg = f2fma(pack2(w, w), rg.y, crg);
                        cb  = fmaf(w, bb.y, cb);
                        T = Tn;
                    }
                }
                if (T < MIN_W) break;
            }
        }
    }

    float cr, cg; unpack2(crg, cr, cg);
    const int px = blockIdx.x * TILE + (tid >> 4);
    const int py = blockIdx.y * TILE + (tid & 15);
    const int o  = (px * H_IMG + py) * 3;
    out[o + 0] = cr;
    out[o + 1] = cg;
    out[o + 2] = cb;
}

extern "C" void kernel_launch(void* const* d_in, const int* in_sizes, int n_in,
                              void* d_out, int out_size) {
    const float* pxy     = (const float*)d_in[0];
    const float* icov    = (const float*)d_in[1];
    const float* radius  = (const float*)d_in[2];
    const float* colors  = (const float*)d_in[3];
    const float* opacity = (const float*)d_in[4];
    float* out = (float*)d_out;

    dim3 grid(W_IMG / TILE, H_IMG / TILE);
    gs_raster_kernel<<<grid, 256>>>(pxy, icov, radius, colors, opacity, out);
}

// round 4
// speedup vs baseline: 1.8871x; 1.2234x over previous
#include <cuda_runtime.h>

#define W_IMG 256
#define H_IMG 256
#define TILE 16
#define NG 8192
#define NSEG 4
#define SEG (NG / NSEG)
#define BATCH 256
#define MIN_W 1e-6f
#define LOG2E 1.4426950408889634f
#define NPIX (W_IMG * H_IMG)
#define UNROLL 8

__device__ float4 g_scratch[NSEG][NPIX];   // (cr, cg, cb, T) per segment per pixel

__device__ __forceinline__ float ex2_fast(float x) {
    float y; asm("ex2.approx.f32 %0, %1;" : "=f"(y) : "f"(x)); return y;
}
__device__ __forceinline__ float lg2_fast(float x) {
    float y; asm("lg2.approx.f32 %0, %1;" : "=f"(y) : "f"(x)); return y;
}

__global__ __launch_bounds__(256)
void gs_raster_kernel(const float* __restrict__ pxy,
                      const float* __restrict__ icov,
                      const float* __restrict__ radius,
                      const float* __restrict__ colors,
                      const float* __restrict__ opacity)
{
    __shared__ float4 s_g1[BATCH];   // -mx, -my, a2, b2
    __shared__ float4 s_g2[BATCH];   // c2, d, col.r, col.g
    __shared__ float  s_cb[BATCH];   // col.b
    __shared__ int    s_wcnt[8];

    const int tid  = threadIdx.x;
    const int lane = tid & 31;
    const int warp = tid >> 5;
    const int seg  = blockIdx.z;

    const float tx0 = (float)(blockIdx.x * TILE);
    const float ty0 = (float)(blockIdx.y * TILE);
    const float tx1 = tx0 + (float)TILE;
    const float ty1 = ty0 + (float)TILE;

    const float fx = tx0 + (float)(tid >> 4);
    const float fy = ty0 + (float)(tid & 15);

    float T  = 1.0f;           // local (per-segment) transmittance
    float cr = 0.0f, cg = 0.0f, cb = 0.0f;

    const int seg_beg = seg * SEG;
    const int seg_end = seg_beg + SEG;

    for (int base = seg_beg; base < seg_end; base += BATCH) {
        // block-wide early exit; also the barrier protecting smem reuse
        if (__syncthreads_count(T >= MIN_W) == 0) break;

        const int g = base + tid;                       // SEG % BATCH == 0
        const float2 mp = ((const float2*)pxy)[g];
        const float  r  = radius[g];
        const bool keep = (floorf(mp.x - r) <= tx1) && (ceilf(mp.x + r) >= tx0)
                       && (floorf(mp.y - r) <= ty1) && (ceilf(mp.y + r) >= ty0);

        const unsigned m = __ballot_sync(0xffffffffu, keep);
        if (lane == 0) s_wcnt[warp] = __popc(m);
        __syncthreads();

        int off = 0, total = 0;
        #pragma unroll
        for (int w = 0; w < 8; ++w) {
            const int c = s_wcnt[w];
            if (w < warp) off += c;
            total += c;
        }
        const int padded = (total + (UNROLL - 1)) & ~(UNROLL - 1);

        if (keep) {
            const int idx = off + __popc(m & ((1u << lane) - 1u));   // order-preserving
            const float4 ic = ((const float4*)icov)[g];
            const float a2 = -0.5f * LOG2E * ic.x;
            const float b2 = -LOG2E * ic.y;
            const float c2 = -0.5f * LOG2E * ic.w;
            const float d  = -lg2_fast(1.0f + ex2_fast(-LOG2E * opacity[g])); // log2(sigmoid)
            s_g1[idx] = make_float4(-mp.x, -mp.y, a2, b2);
            s_g2[idx] = make_float4(c2, d, colors[3*g+0], colors[3*g+1]);
            s_cb[idx] = colors[3*g+2];
        }
        if (tid >= total && tid < padded) {            // sentinel: alpha == 0 exactly
            s_g1[tid] = make_float4(0.0f, 0.0f, 0.0f, 0.0f);
            s_g2[tid] = make_float4(0.0f, -1e30f, 0.0f, 0.0f);
            s_cb[tid] = 0.0f;
        }
        __syncthreads();

        if (T >= MIN_W) {
            for (int j = 0; j < padded; j += UNROLL) {
                float al[UNROLL];
                #pragma unroll
                for (int k = 0; k < UNROLL; ++k) {      // independent alpha evals
                    const float4 g1 = s_g1[j + k];
                    const float4 g2 = s_g2[j + k];
                    const float dx = fx + g1.x;
                    const float dy = fy + g1.y;
                    float u = fmaf(g1.z, dx, g1.w * dy);
                    float q = fmaf(g2.x * dy, dy, g2.y);
                    q = fmaf(u, dx, q);
                    al[k] = ex2_fast(q);                // exp(-q/2)*sigmoid(op)
                }
                #pragma unroll
                for (int k = 0; k < UNROLL; ++k) {      // short serial T-chain
                    const float Tn = fmaf(-al[k], T, T);
                    const float w  = (Tn >= MIN_W) ? T * al[k] : 0.0f;
                    const float4 g2 = s_g2[j + k];
                    cr = fmaf(w, g2.z, cr);
                    cg = fmaf(w, g2.w, cg);
                    cb = fmaf(w, s_cb[j + k], cb);
                    T = Tn;
                }
                if (T < MIN_W) break;
            }
        }
    }

    const int px = blockIdx.x * TILE + (tid >> 4);
    const int py = blockIdx.y * TILE + (tid & 15);
    g_scratch[seg][px * H_IMG + py] = make_float4(cr, cg, cb, T);
}

__global__ __launch_bounds__(256)
void gs_combine_kernel(float* __restrict__ out)
{
    const int i = blockIdx.x * 256 + threadIdx.x;      // pixel index
    const float4 s0 = g_scratch[0][i];
    const float4 s1 = g_scratch[1][i];
    const float4 s2 = g_scratch[2][i];
    const float4 s3 = g_scratch[3][i];
    // color = c0 + T0*(c1 + T1*(c2 + T2*c3))
    float cr = fmaf(s2.w, s3.x, s2.x);
    float cg = fmaf(s2.w, s3.y, s2.y);
    float cb = fmaf(s2.w, s3.z, s2.z);
    cr = fmaf(s1.w, cr, s1.x);
    cg = fmaf(s1.w, cg, s1.y);
    cb = fmaf(s1.w, cb, s1.z);
    cr = fmaf(s0.w, cr, s0.x);
    cg = fmaf(s0.w, cg, s0.y);
    cb = fmaf(s0.w, cb, s0.z);
    out[3*i + 0] = cr;
    out[3*i + 1] = cg;
    out[3*i + 2] = cb;
}

extern "C" void kernel_launch(void* const* d_in, const int* in_sizes, int n_in,
                              void* d_out, int out_size) {
    const float* pxy     = (const float*)d_in[0];
    const float* icov    = (const float*)d_in[1];
    const float* radius  = (const float*)d_in[2];
    const float* colors  = (const float*)d_in[3];
    const float* opacity = (const float*)d_in[4];
    float* out = (float*)d_out;

    dim3 grid(W_IMG / TILE, H_IMG / TILE, NSEG);
    gs_raster_kernel<<<grid, 256>>>(pxy, icov, radius, colors, opacity);
    gs_combine_kernel<<<NPIX / 256, 256>>>(out);
}

// round 5
// speedup vs baseline: 1.9542x; 1.0356x over previous
#include <cuda_runtime.h>

#define W_IMG 256
#define H_IMG 256
#define TILE 16
#define NG 8192
#define NSEG 4
#define SEG (NG / NSEG)
#define BATCH 256
#define MIN_W 1e-6f
#define LOG2E 1.4426950408889634f
#define NPIX (W_IMG * H_IMG)

typedef unsigned long long u64;
typedef unsigned int u32;

__device__ float4 g_scratch[NSEG][NPIX];  // (cr,cg,cb,T) per segment per pixel
__device__ u32    g_bbox[NG];             // packed tile range bytes: tlx, tly, 15-thx, 15-thy
__device__ float4 g_pa[NG];               // -mx, -my, a2, b2
__device__ float4 g_pb[NG];               // c2, d, col.r, col.g
__device__ float  g_pc[NG];               // col.b

__device__ __forceinline__ float ex2_fast(float x) {
    float y; asm("ex2.approx.f32 %0, %1;" : "=f"(y) : "f"(x)); return y;
}
__device__ __forceinline__ float lg2_fast(float x) {
    float y; asm("lg2.approx.f32 %0, %1;" : "=f"(y) : "f"(x)); return y;
}
__device__ __forceinline__ u64 pack2(float lo, float hi) {
    u64 r; asm("mov.b64 %0, {%1, %2};" : "=l"(r) : "f"(lo), "f"(hi)); return r;
}
__device__ __forceinline__ void unpack2(u64 v, float& lo, float& hi) {
    asm("mov.b64 {%0, %1}, %2;" : "=f"(lo), "=f"(hi) : "l"(v));
}
__device__ __forceinline__ u64 f2add(u64 a, u64 b) {
    u64 d; asm("add.rn.f32x2 %0, %1, %2;" : "=l"(d) : "l"(a), "l"(b)); return d;
}
__device__ __forceinline__ u64 f2mul(u64 a, u64 b) {
    u64 d; asm("mul.rn.f32x2 %0, %1, %2;" : "=l"(d) : "l"(a), "l"(b)); return d;
}
__device__ __forceinline__ u64 f2fma(u64 a, u64 b, u64 c) {
    u64 d; asm("fma.rn.f32x2 %0, %1, %2, %3;" : "=l"(d) : "l"(a), "l"(b), "l"(c)); return d;
}
__device__ __forceinline__ int iclamp(int v, int lo, int hi) {
    return v < lo ? lo : (v > hi ? hi : v);
}

// ---------------- prep: per-gaussian constants + packed tile range -------------
__global__ __launch_bounds__(256)
void gs_prep_kernel(const float* __restrict__ pxy,
                    const float* __restrict__ icov,
                    const float* __restrict__ radius,
                    const float* __restrict__ colors,
                    const float* __restrict__ opacity)
{
    const int g = blockIdx.x * 256 + threadIdx.x;
    const float2 mp = ((const float2*)pxy)[g];
    const float  r  = radius[g];

    // integer-valued bbox per reference
    const float mnx = floorf(mp.x - r), mxx = ceilf(mp.x + r);
    const float mny = floorf(mp.y - r), mxy = ceilf(mp.y + r);
    // tile x participates iff mnx <= 16(tx+1) && mxx >= 16tx  ->  tx in [tlx, thx]
    const int tlx = (int)floorf((mnx - 1.0f) * 0.0625f);   // ceil((mnx-16)/16)
    const int thx = (int)floorf(mxx * 0.0625f);
    const int tly = (int)floorf((mny - 1.0f) * 0.0625f);
    const int thy = (int)floorf(mxy * 0.0625f);
    const u32 b0 = (u32)iclamp(tlx, 0, 255);
    const u32 b1 = (u32)iclamp(tly, 0, 255);
    const u32 b2 = (u32)iclamp(15 - thx, 0, 255);
    const u32 b3 = (u32)iclamp(15 - thy, 0, 255);
    g_bbox[g] = b0 | (b1 << 8) | (b2 << 16) | (b3 << 24);

    const float4 ic = ((const float4*)icov)[g];
    const float a2 = -0.5f * LOG2E * ic.x;
    const float bb = -LOG2E * ic.y;
    const float c2 = -0.5f * LOG2E * ic.w;
    const float d  = -lg2_fast(1.0f + ex2_fast(-LOG2E * opacity[g])); // log2(sigmoid)
    g_pa[g] = make_float4(-mp.x, -mp.y, a2, bb);
    g_pb[g] = make_float4(c2, d, colors[3*g+0], colors[3*g+1]);
    g_pc[g] = colors[3*g+2];
}

// ---------------- raster: one block per (tile, depth segment) -----------------
__global__ __launch_bounds__(256, 5)
void gs_raster_kernel()
{
    // pair-interleaved: slot j holds gaussians (2j, 2j+1)
    __shared__ ulonglong2 s_m [BATCH/2];  // (-mx pair), (-my pair)
    __shared__ ulonglong2 s_ab[BATCH/2];  // (a2 pair), (b2 pair)
    __shared__ ulonglong2 s_cd[BATCH/2];  // (c2 pair), (d pair)
    __shared__ ulonglong2 s_rg[BATCH/2];  // (r,g even), (r,g odd)
    __shared__ float2     s_b [BATCH/2];  // (cb even, cb odd)
    __shared__ int        s_wcnt[8];

    const int tid  = threadIdx.x;
    const int lane = tid & 31;
    const int warp = tid >> 5;
    const int seg  = blockIdx.z;
    const int tx   = blockIdx.x;
    const int ty   = blockIdx.y;

    // packed tile vector for the byte-wise cull compare
    const u32 tvec = (u32)tx | ((u32)ty << 8) | ((u32)(15 - tx) << 16) | ((u32)(15 - ty) << 24);

    const float fx = (float)(tx * TILE + (tid >> 4));
    const float fy = (float)(ty * TILE + (tid & 15));
    const u64 fxp = pack2(fx, fx);
    const u64 fyp = pack2(fy, fy);

    float T = 1.0f;
    u64   crg = pack2(0.0f, 0.0f);
    float cb  = 0.0f;

    const int seg_beg = seg * SEG;
    const int seg_end = seg_beg + SEG;

    for (int base = seg_beg; base < seg_end; base += BATCH) {
        if (__syncthreads_count(T >= MIN_W) == 0) break;

        const int g = base + tid;
        const bool keep = (__vcmpleu4(g_bbox[g], tvec) == 0xffffffffu);

        const unsigned m = __ballot_sync(0xffffffffu, keep);
        if (lane == 0) s_wcnt[warp] = __popc(m);
        __syncthreads();

        int off = 0, total = 0;
        #pragma unroll
        for (int w = 0; w < 8; ++w) {
            const int c = s_wcnt[w];
            if (w < warp) off += c;
            total += c;
        }
        const int padded = (total + 7) & ~7;

        if (keep) {
            const int idx = off + __popc(m & ((1u << lane) - 1u));   // order-preserving
            const int j = idx >> 1, e = idx & 1;
            const float4 A = g_pa[g];
            const float4 B = g_pb[g];
            float* pm  = (float*)&s_m[j];  pm[e]  = A.x; pm[2+e]  = A.y;
            float* pab = (float*)&s_ab[j]; pab[e] = A.z; pab[2+e] = A.w;
            float* pcd = (float*)&s_cd[j]; pcd[e] = B.x; pcd[2+e] = B.y;
            float* prg = (float*)&s_rg[j]; prg[2*e] = B.z; prg[2*e+1] = B.w;
            ((float*)&s_b[j])[e] = g_pc[g];
        }
        if (tid >= total && tid < padded) {        // sentinel: alpha == 0 exactly
            const int j = tid >> 1, e = tid & 1;
            float* pm  = (float*)&s_m[j];  pm[e]  = 0.0f; pm[2+e]  = 0.0f;
            float* pab = (float*)&s_ab[j]; pab[e] = 0.0f; pab[2+e] = 0.0f;
            float* pcd = (float*)&s_cd[j]; pcd[e] = 0.0f; pcd[2+e] = -1e30f;
            float* prg = (float*)&s_rg[j]; prg[2*e] = 0.0f; prg[2*e+1] = 0.0f;
            ((float*)&s_b[j])[e] = 0.0f;
        }
        __syncthreads();

        if (T >= MIN_W) {
            const int npair = padded >> 1;
            for (int j = 0; j < npair; j += 4) {    // 4 pairs = 8 gaussians
                float al[8];
                #pragma unroll
                for (int p = 0; p < 4; ++p) {
                    const ulonglong2 mm = s_m [j + p];
                    const ulonglong2 ab = s_ab[j + p];
                    const ulonglong2 cd = s_cd[j + p];
                    const u64 dx = f2add(fxp, mm.x);
                    const u64 dy = f2add(fyp, mm.y);
                    const u64 t1 = f2fma(ab.x, dx, f2mul(ab.y, dy));   // a2*dx + b2*dy
                    const u64 t2 = f2fma(f2mul(cd.x, dy), dy, cd.y);   // c2*dy^2 + d
                    const u64 q  = f2fma(t1, dx, t2);
                    float q0, q1; unpack2(q, q0, q1);
                    al[2*p]   = ex2_fast(q0);
                    al[2*p+1] = ex2_fast(q1);
                }
                #pragma unroll
                for (int p = 0; p < 4; ++p) {
                    const ulonglong2 rg = s_rg[j + p];
                    const float2     bv = s_b [j + p];
                    {
                        const float a  = al[2*p];
                        const float Tn = fmaf(-a, T, T);
                        const float w  = (Tn >= MIN_W) ? T * a : 0.0f;
                        crg = f2fma(pack2(w, w), rg.x, crg);
                        cb  = fmaf(w, bv.x, cb);
                        T = Tn;
                    }
                    {
                        const float a  = al[2*p+1];
                        const float Tn = fmaf(-a, T, T);
                        const float w  = (Tn >= MIN_W) ? T * a : 0.0f;
                        crg = f2fma(pack2(w, w), rg.y, crg);
                        cb  = fmaf(w, bv.y, cb);
                        T = Tn;
                    }
                }
                if (T < MIN_W) break;
            }
        }
    }

    float cr, cg; unpack2(crg, cr, cg);
    const int px = tx * TILE + (tid >> 4);
    const int py = ty * TILE + (tid & 15);
    g_scratch[seg][px * H_IMG + py] = make_float4(cr, cg, cb, T);
}

// ---------------- combine ------------------------------------------------------
__global__ __launch_bounds__(256)
void gs_combine_kernel(float* __restrict__ out)
{
    const int i = blockIdx.x * 256 + threadIdx.x;
    const float4 s0 = g_scratch[0][i];
    const float4 s1 = g_scratch[1][i];
    const float4 s2 = g_scratch[2][i];
    const float4 s3 = g_scratch[3][i];
    float cr = fmaf(s2.w, s3.x, s2.x);
    float cg = fmaf(s2.w, s3.y, s2.y);
    float cb = fmaf(s2.w, s3.z, s2.z);
    cr = fmaf(s1.w, cr, s1.x);
    cg = fmaf(s1.w, cg, s1.y);
    cb = fmaf(s1.w, cb, s1.z);
    cr = fmaf(s0.w, cr, s0.x);
    cg = fmaf(s0.w, cg, s0.y);
    cb = fmaf(s0.w, cb, s0.z);
    out[3*i + 0] = cr;
    out[3*i + 1] = cg;
    out[3*i + 2] = cb;
}

extern "C" void kernel_launch(void* const* d_in, const int* in_sizes, int n_in,
                              void* d_out, int out_size) {
    const float* pxy     = (const float*)d_in[0];
    const float* icov    = (const float*)d_in[1];
    const float* radius  = (const float*)d_in[2];
    const float* colors  = (const float*)d_in[3];
    const float* opacity = (const float*)d_in[4];
    float* out = (float*)d_out;

    gs_prep_kernel<<<NG / 256, 256>>>(pxy, icov, radius, colors, opacity);
    dim3 grid(W_IMG / TILE, H_IMG / TILE, NSEG);
    gs_raster_kernel<<<grid, 256>>>();
    gs_combine_kernel<<<NPIX / 256, 256>>>(out);
}